// round 1
// baseline (speedup 1.0000x reference)
#include <cuda_runtime.h>

// ConstituencyMFVI: B=8, N=192, MAX_ITER=3
//   q[b,i,j] <- s_span[b,i,j] + sum_{k != i, k != j} sigmoid(q)[b,i,k] * s_pair[b,i,j,k]   (j > i)
//   q[b,i,j] = s_span[b,i,j]                                                              (j <= i)
//   out = sigmoid(q) after 3 iterations.
//
// One CTA per (b,i). SP tile rows j=i+1..191 cached in SMEM (pad 193 for
// conflict-free column access). All 3 iterations run from SMEM; s_pair rows
// with j<=i are never touched (halves HBM traffic).

#define NDIM 192
#define PAD  193
#define NITER 3
#define THREADS 256

static const int SMEM_BYTES = (NDIM * PAD + NDIM) * (int)sizeof(float);

__global__ void __launch_bounds__(THREADS, 1)
mfvi_kernel(const float* __restrict__ s_span,
            const float* __restrict__ s_pair,
            float* __restrict__ out)
{
    extern __shared__ float smem[];
    float* sp  = smem;                 // [NDIM][PAD], rows i+1..191 valid
    float* sig = smem + NDIM * PAD;    // [NDIM]

    const int bi  = blockIdx.x;        // b*192 + i
    const int i   = bi % NDIM;
    const int tid = threadIdx.x;

    // ---- Load SP rows j = i+1 .. 191 (contiguous block in gmem) ----
    const int rowStart = i + 1;
    const int nf4 = (NDIM - rowStart) * (NDIM / 4);   // float4 count
    const float4* gsrc = reinterpret_cast<const float4*>(
        s_pair + (size_t)bi * (NDIM * NDIM) + (size_t)rowStart * NDIM);

    for (int idx = tid; idx < nf4; idx += THREADS) {
        int j = rowStart + idx / (NDIM / 4);
        int c = (idx % (NDIM / 4)) * 4;
        float4 v = gsrc[idx];
        float* dst = sp + j * PAD + c;   // pad 193 -> scalar stores
        dst[0] = v.x; dst[1] = v.y; dst[2] = v.z; dst[3] = v.w;
    }

    // ---- Per-thread state: thread j owns output element j ----
    const int j = tid;
    float span_j = 0.0f, q_j = 0.0f;
    if (j < NDIM) {
        span_j = s_span[(size_t)bi * NDIM + j];
        q_j = span_j;
    }
    __syncthreads();

    // ---- 3 mean-field iterations, all from SMEM ----
    #pragma unroll
    for (int it = 0; it < NITER; ++it) {
        if (j < NDIM)
            sig[j] = 1.0f / (1.0f + __expf(-q_j));
        __syncthreads();

        if (j > i && j < NDIM) {
            const float* row = sp + j * PAD;
            // 4-way split accumulation for ILP
            float d0 = 0.f, d1 = 0.f, d2 = 0.f, d3 = 0.f;
            #pragma unroll 4
            for (int k = 0; k < NDIM; k += 4) {
                d0 += sig[k + 0] * row[k + 0];
                d1 += sig[k + 1] * row[k + 1];
                d2 += sig[k + 2] * row[k + 2];
                d3 += sig[k + 3] * row[k + 3];
            }
            float d = (d0 + d1) + (d2 + d3);
            // remove excluded terms k==i and k==j
            d -= sig[i] * row[i] + sig[j] * row[j];
            q_j = span_j + d;
        }
        __syncthreads();   // protect sig[] before next-iteration overwrite
    }

    if (j < NDIM)
        out[(size_t)bi * NDIM + j] = 1.0f / (1.0f + __expf(-q_j));
}

extern "C" void kernel_launch(void* const* d_in, const int* in_sizes, int n_in,
                              void* d_out, int out_size)
{
    (void)in_sizes; (void)n_in; (void)out_size;
    const float* s_span = (const float*)d_in[0];
    const float* s_pair = (const float*)d_in[1];
    // d_in[2] = mask: analytic (strict upper triangle), not needed.
    float* out = (float*)d_out;

    cudaFuncSetAttribute(mfvi_kernel,
                         cudaFuncAttributeMaxDynamicSharedMemorySize, SMEM_BYTES);

    const int grid = 8 * NDIM;   // B * N = 1536 CTAs, one per (b,i)
    mfvi_kernel<<<grid, THREADS, SMEM_BYTES>>>(s_span, s_pair, out);
}

// round 2
// speedup vs baseline: 1.4532x; 1.4532x over previous
#include <cuda_runtime.h>

// ConstituencyMFVI: B=8, N=192, 3 iterations.
// One CTA per (b,i). Rows j=i+1..191 of s_pair[b,i] cached in SMEM (pad 196
// for 16B-aligned, conflict-free LDS.128 column access). cp.async loads in 4
// chunks; iteration 1 (weights = sigmoid(s_span)) is computed per-chunk as
// data arrives, overlapping the full HBM load. Masked cells (k==i, k==j)
// zeroed once in SMEM -> no per-iteration corrections.
// 384 threads: thread t handles row jj = t%192, k-half h = t/192.

#define NDIM   192
#define RPAD   196
#define NF4ROW 48          // 192/4 float4 per row
#define THREADS 384

static const int SP_FLOATS  = NDIM * RPAD;                       // 37632
static const int SMEM_BYTES = (SP_FLOATS + NDIM + THREADS) * 4;  // ~152.8 KB

__device__ __forceinline__ unsigned smem_u32(const void* p) {
    return (unsigned)__cvta_generic_to_shared(p);
}

__device__ __forceinline__ float sigmoidf_(float x) {
    return 1.0f / (1.0f + __expf(-x));
}

__global__ void __launch_bounds__(THREADS, 1)
mfvi_kernel(const float* __restrict__ s_span,
            const float* __restrict__ s_pair,
            float* __restrict__ out)
{
    extern __shared__ float smem[];
    float* sp      = smem;                    // [NDIM][RPAD], rows i+1..191
    float* sig     = smem + SP_FLOATS;        // [NDIM] sigmoid(q), 16B aligned
    float* partial = sig + NDIM;              // [THREADS]

    const int bi  = blockIdx.x;               // b*192 + i
    const int i   = bi % NDIM;
    const int tid = threadIdx.x;
    const int jj  = tid % NDIM;               // row this thread works on
    const int h   = tid / NDIM;               // k-half: [96h, 96h+96)

    const int rowStart = i + 1;
    const int nRows    = NDIM - rowStart;
    const int rpc      = (nRows + 3) >> 2;    // rows per chunk

    const float* gbase = s_pair + (size_t)bi * (NDIM * NDIM);

    // ---- Issue cp.async loads, 4 commit groups (chunks of rows) ----
    #pragma unroll
    for (int c = 0; c < 4; ++c) {
        int ra = rowStart + c * rpc;       if (ra > NDIM) ra = NDIM;
        int rb = ra + rpc;                 if (rb > NDIM) rb = NDIM;
        int f0 = (ra - rowStart) * NF4ROW;
        int f1 = (rb - rowStart) * NF4ROW;
        for (int idx = f0 + tid; idx < f1; idx += THREADS) {
            int j   = rowStart + idx / NF4ROW;
            int col = (idx % NF4ROW) * 4;
            const float* src = gbase + (size_t)j * NDIM + col;
            unsigned dst = smem_u32(sp + j * RPAD + col);
            asm volatile("cp.async.cg.shared.global [%0], [%1], 16;"
                         :: "r"(dst), "l"(src));
        }
        asm volatile("cp.async.commit_group;");
    }

    // ---- q0 = span; sig0 = sigmoid(span) (k-weights for fused iter 1) ----
    float span_j = 0.0f, q_j = 0.0f, out_sig = 0.5f;
    if (tid < NDIM) {
        span_j = s_span[(size_t)bi * NDIM + tid];
        q_j    = span_j;
        out_sig = sigmoidf_(q_j);
        sig[tid] = out_sig;
    }
    __syncthreads();   // sig0 visible before any chunk compute

    const float4* sig4 = reinterpret_cast<const float4*>(sig) + h * 24;

    // ---- Iteration 1, fused with chunk arrival ----
    float a0 = 0.f, a1 = 0.f, a2 = 0.f, a3 = 0.f;

    #define CHUNK(C, WAITN)                                                     \
    {                                                                           \
        int ra = rowStart + (C) * rpc;  if (ra > NDIM) ra = NDIM;               \
        int rb = ra + rpc;              if (rb > NDIM) rb = NDIM;               \
        asm volatile("cp.async.wait_group %0;" :: "n"(WAITN));                  \
        __syncthreads();                                                        \
        int nz = 2 * (rb - ra);                                                 \
        for (int z = tid; z < nz; z += THREADS) {                               \
            int r = ra + (z >> 1);                                              \
            sp[r * RPAD + ((z & 1) ? i : r)] = 0.0f;   /* mask k==i, k==j */    \
        }                                                                       \
        __syncthreads();                                                        \
        if (jj >= ra && jj < rb) {                                              \
            const float4* row4 =                                                \
                reinterpret_cast<const float4*>(sp + jj * RPAD + h * 96);       \
            _Pragma("unroll")                                                   \
            for (int r = 0; r < 24; ++r) {                                      \
                float4 v = row4[r]; float4 s = sig4[r];                         \
                a0 += v.x * s.x; a1 += v.y * s.y;                               \
                a2 += v.z * s.z; a3 += v.w * s.w;                               \
            }                                                                   \
        }                                                                       \
    }
    CHUNK(0, 3) CHUNK(1, 2) CHUNK(2, 1) CHUNK(3, 0)
    #undef CHUNK

    partial[tid] = (a0 + a1) + (a2 + a3);
    __syncthreads();
    if (tid < NDIM) {
        if (tid > i) q_j = span_j + partial[tid] + partial[tid + NDIM];
        out_sig = sigmoidf_(q_j);
        sig[tid] = out_sig;
    }

    // ---- Iterations 2..3, fully from SMEM ----
    #pragma unroll
    for (int it = 0; it < 2; ++it) {
        __syncthreads();   // new sig visible
        float d0 = 0.f, d1 = 0.f, d2 = 0.f, d3 = 0.f;
        if (jj > i) {
            const float4* row4 =
                reinterpret_cast<const float4*>(sp + jj * RPAD + h * 96);
            #pragma unroll
            for (int r = 0; r < 24; ++r) {
                float4 v = row4[r]; float4 s = sig4[r];
                d0 += v.x * s.x; d1 += v.y * s.y;
                d2 += v.z * s.z; d3 += v.w * s.w;
            }
        }
        partial[tid] = (d0 + d1) + (d2 + d3);
        __syncthreads();
        if (tid < NDIM) {
            if (tid > i) q_j = span_j + partial[tid] + partial[tid + NDIM];
            out_sig = sigmoidf_(q_j);
            sig[tid] = out_sig;
        }
    }

    // ---- Output: marginals = sigmoid(q) after 3 iterations ----
    if (tid < NDIM)
        out[(size_t)bi * NDIM + tid] = out_sig;
}

extern "C" void kernel_launch(void* const* d_in, const int* in_sizes, int n_in,
                              void* d_out, int out_size)
{
    (void)in_sizes; (void)n_in; (void)out_size;
    const float* s_span = (const float*)d_in[0];
    const float* s_pair = (const float*)d_in[1];
    // d_in[2] = mask: analytic (strict upper triangle), not needed.
    float* out = (float*)d_out;

    cudaFuncSetAttribute(mfvi_kernel,
                         cudaFuncAttributeMaxDynamicSharedMemorySize, SMEM_BYTES);

    const int grid = 8 * NDIM;   // one CTA per (b,i)
    mfvi_kernel<<<grid, THREADS, SMEM_BYTES>>>(s_span, s_pair, out);
}